// round 2
// baseline (speedup 1.0000x reference)
#include <cuda_runtime.h>

#define DIM   48
#define NBINS 38
#define TILE  128      // rows per block
#define PAD   49       // padded smem row stride (floats) -> conflict-free (gcd(17,32)=1)

#define BIN_LO   3.25f
#define BIN_STEP (17.5f / 37.0f)    // linspace(3.25, 20.75, 38) spacing
#define BIN_INV  (37.0f / 17.5f)

// ---------------------------------------------------------------------------
// single_out = layernorm(single)  — 1024 rows x 48, negligible cost
// ---------------------------------------------------------------------------
__global__ void single_ln_kernel(const float* __restrict__ single,
                                 const float* __restrict__ gamma,
                                 const float* __restrict__ beta,
                                 float* __restrict__ out, int L) {
    int row = blockIdx.x;
    if (row >= L) return;
    int t = threadIdx.x;                       // 48 threads
    __shared__ float s[DIM];
    __shared__ float mu_s, rs_s;
    float v = single[(size_t)row * DIM + t];
    s[t] = v;
    __syncthreads();
    if (t == 0) {
        float sum = 0.f, ss = 0.f;
        #pragma unroll
        for (int e = 0; e < DIM; e++) { float u = s[e]; sum += u; ss += u * u; }
        float m   = sum * (1.0f / DIM);
        float var = ss * (1.0f / DIM) - m * m;
        mu_s = m;
        rs_s = rsqrtf(var + 1e-5f);
    }
    __syncthreads();
    out[(size_t)row * DIM + t] = (v - mu_s) * rs_s * gamma[t] + beta[t];
}

// ---------------------------------------------------------------------------
// pair_out = layernorm(pair) + (W[bin(d(i,j))] + b)
// ---------------------------------------------------------------------------
__global__ __launch_bounds__(TILE) void pair_kernel(
    const float* __restrict__ x,
    const float* __restrict__ pair,
    const float* __restrict__ W,
    const float* __restrict__ bvec,
    const float* __restrict__ gamma,
    const float* __restrict__ beta,
    float* __restrict__ out, int L)
{
    __shared__ float tile[TILE * PAD];
    __shared__ float sWb[NBINS * PAD];   // W row + bias, folded
    __shared__ float sg[DIM], sbe[DIM];

    const int  tid   = threadIdx.x;
    const long base  = (long)blockIdx.x * TILE;       // first global row of tile
    const long total = (long)L * L;

    // --- load constants: W+b folded, gamma, beta ---
    for (int idx = tid; idx < NBINS * DIM; idx += TILE) {
        int k = idx / DIM, e = idx % DIM;
        sWb[k * PAD + e] = W[idx] + bvec[e];
    }
    if (tid < DIM) { sg[tid] = gamma[tid]; sbe[tid] = beta[tid]; }

    // --- staging: coalesced float4 loads of the tile (TILE rows * 12 float4) ---
    const float4* src = reinterpret_cast<const float4*>(pair) + base * (DIM / 4);
    #pragma unroll
    for (int p = 0; p < 12; p++) {
        int g = tid + p * TILE;                    // float4 index within tile
        int r = g / 12, m = g % 12;
        if (base + r < total) {
            float4 v = src[g];
            float* dst = &tile[r * PAD + m * 4];
            dst[0] = v.x; dst[1] = v.y; dst[2] = v.z; dst[3] = v.w;
        }
    }

    // --- per-thread row: distance -> nearest bin (step = 17.5/37) ---
    const long grow  = base + tid;
    const bool valid = (grow < total);
    int kbin = 0;
    if (valid) {
        int i = (int)(grow / L), j = (int)(grow % L);
        float dx = x[3 * i]     - x[3 * j];
        float dy = x[3 * i + 1] - x[3 * j + 1];
        float dz = x[3 * i + 2] - x[3 * j + 2];
        float d  = sqrtf(dx * dx + dy * dy + dz * dz + 1e-12f);
        int k = (int)rintf((d - BIN_LO) * BIN_INV);
        k = k < 0 ? 0 : (k > NBINS - 1 ? NBINS - 1 : k);
        // ±1 neighbor refinement against exact bin centers (guards fp rounding)
        float best = fabsf(d - fmaf((float)k, BIN_STEP, BIN_LO));
        if (k > 0) {
            float c = fabsf(d - fmaf((float)(k - 1), BIN_STEP, BIN_LO));
            if (c < best) { best = c; k = k - 1; }
        }
        if (k < NBINS - 1) {
            float c = fabsf(d - fmaf((float)(k + 1), BIN_STEP, BIN_LO));
            if (c < best) { k = k + 1; }
        }
        kbin = k;
    }
    __syncthreads();

    // --- layernorm + embedding add, in place in smem (conflict-free) ---
    if (valid) {
        float sum = 0.f, ss = 0.f;
        #pragma unroll
        for (int e = 0; e < DIM; e++) {
            float v = tile[tid * PAD + e];
            sum += v; ss += v * v;
        }
        float m   = sum * (1.0f / DIM);
        float var = ss * (1.0f / DIM) - m * m;
        float rs  = rsqrtf(var + 1e-5f);
        const float* wrow = &sWb[kbin * PAD];
        #pragma unroll
        for (int e = 0; e < DIM; e++) {
            float v = tile[tid * PAD + e];
            tile[tid * PAD + e] = (v - m) * rs * sg[e] + sbe[e] + wrow[e];
        }
    }
    __syncthreads();

    // --- coalesced float4 stores ---
    float4* dst = reinterpret_cast<float4*>(out) + base * (DIM / 4);
    #pragma unroll
    for (int p = 0; p < 12; p++) {
        int g = tid + p * TILE;
        int r = g / 12, m = g % 12;
        if (base + r < total) {
            const float* s = &tile[r * PAD + m * 4];
            dst[g] = make_float4(s[0], s[1], s[2], s[3]);
        }
    }
}

// ---------------------------------------------------------------------------
extern "C" void kernel_launch(void* const* d_in, const int* in_sizes, int n_in,
                              void* d_out, int out_size) {
    const float* x      = (const float*)d_in[0];
    const float* single = (const float*)d_in[1];
    const float* pair   = (const float*)d_in[2];
    const float* W      = (const float*)d_in[3];
    const float* b      = (const float*)d_in[4];
    const float* gp     = (const float*)d_in[5];
    const float* bp     = (const float*)d_in[6];
    const float* gm     = (const float*)d_in[7];
    const float* bm     = (const float*)d_in[8];

    const int L = in_sizes[1] / DIM;            // single is [1, L, DIM]

    float* out        = (float*)d_out;
    float* single_out = out;                     // reference returns (single_out, pair_out)
    float* pair_out   = out + (size_t)L * DIM;

    single_ln_kernel<<<L, DIM>>>(single, gm, bm, single_out, L);

    long total  = (long)L * L;
    int  blocks = (int)((total + TILE - 1) / TILE);
    pair_kernel<<<blocks, TILE>>>(x, pair, W, b, gp, bp, pair_out, L);
}

// round 3
// speedup vs baseline: 2.2282x; 2.2282x over previous
#include <cuda_runtime.h>

#define DIM   48
#define NBINS 38

#define BIN_LO   3.25f
#define BIN_STEP (17.5f / 37.0f)    // linspace(3.25, 20.75, 38) spacing
#define BIN_INV  (37.0f / 17.5f)

// 4 threads per row; DIM=48 -> 3 float4 per thread at float4-offsets t, t+4, t+8.
// Row reduction via 2 butterfly shuffles inside the 4-lane group. No shared memory,
// no barriers; every pair element moves exactly once in and once out.

__device__ __forceinline__ int bin_of(float d) {
    int k = (int)rintf((d - BIN_LO) * BIN_INV);
    k = k < 0 ? 0 : (k > NBINS - 1 ? NBINS - 1 : k);
    float best = fabsf(d - fmaf((float)k, BIN_STEP, BIN_LO));
    if (k > 0) {
        float c = fabsf(d - fmaf((float)(k - 1), BIN_STEP, BIN_LO));
        if (c < best) { best = c; k = k - 1; }
    }
    if (k < NBINS - 1) {
        float c = fabsf(d - fmaf((float)(k + 1), BIN_STEP, BIN_LO));
        if (c < best) { k = k + 1; }
    }
    return k;
}

__global__ __launch_bounds__(256, 4) void pair_kernel(
    const float*  __restrict__ x,
    const float4* __restrict__ pair4,
    const float4* __restrict__ W4,
    const float4* __restrict__ b4,
    const float4* __restrict__ g4,
    const float4* __restrict__ be4,
    float4*       __restrict__ out4,
    int L, int total)
{
    const int gtid  = blockIdx.x * 256 + threadIdx.x;
    const int lane4 = gtid & 3;
    const int row   = gtid >> 2;
    if (row >= total) return;

    // --- load 12 elements of this row (lane-strided float4) ---
    const float4* p = pair4 + (size_t)row * 12 + lane4;
    float4 v0 = p[0], v1 = p[4], v2 = p[8];

    // --- row stats via 4-lane butterfly ---
    float sum = v0.x + v0.y + v0.z + v0.w
              + v1.x + v1.y + v1.z + v1.w
              + v2.x + v2.y + v2.z + v2.w;
    float ssq = v0.x*v0.x + v0.y*v0.y + v0.z*v0.z + v0.w*v0.w
              + v1.x*v1.x + v1.y*v1.y + v1.z*v1.z + v1.w*v1.w
              + v2.x*v2.x + v2.y*v2.y + v2.z*v2.z + v2.w*v2.w;
    sum += __shfl_xor_sync(0xffffffffu, sum, 1);
    ssq += __shfl_xor_sync(0xffffffffu, ssq, 1);
    sum += __shfl_xor_sync(0xffffffffu, sum, 2);
    ssq += __shfl_xor_sync(0xffffffffu, ssq, 2);

    const float m   = sum * (1.0f / DIM);
    const float var = ssq * (1.0f / DIM) - m * m;
    const float rs  = rsqrtf(var + 1e-5f);

    // --- distance -> bin (redundant per lane; x is L1-resident) ---
    const int i = row / L, j = row - i * L;
    const float dx = x[3*i]   - x[3*j];
    const float dy = x[3*i+1] - x[3*j+1];
    const float dz = x[3*i+2] - x[3*j+2];
    const float d  = sqrtf(dx*dx + dy*dy + dz*dz + 1e-12f);
    const int kbin = bin_of(d);

    // --- epilogue: (v-m)*rs*gamma + beta + W[kbin] ---
    const float4* wr = W4 + kbin * 12 + lane4;
    float4 w0 = wr[0],    w1 = wr[4],    w2 = wr[8];
    float4 G0 = g4[lane4],  G1 = g4[lane4+4],  G2 = g4[lane4+8];
    float4 B0 = be4[lane4], B1 = be4[lane4+4], B2 = be4[lane4+8];
    float4 c0 = b4[lane4],  c1 = b4[lane4+4],  c2 = b4[lane4+8];

    float4 o0, o1, o2;
    o0.x = fmaf((v0.x - m) * rs, G0.x, B0.x + c0.x + w0.x);
    o0.y = fmaf((v0.y - m) * rs, G0.y, B0.y + c0.y + w0.y);
    o0.z = fmaf((v0.z - m) * rs, G0.z, B0.z + c0.z + w0.z);
    o0.w = fmaf((v0.w - m) * rs, G0.w, B0.w + c0.w + w0.w);
    o1.x = fmaf((v1.x - m) * rs, G1.x, B1.x + c1.x + w1.x);
    o1.y = fmaf((v1.y - m) * rs, G1.y, B1.y + c1.y + w1.y);
    o1.z = fmaf((v1.z - m) * rs, G1.z, B1.z + c1.z + w1.z);
    o1.w = fmaf((v1.w - m) * rs, G1.w, B1.w + c1.w + w1.w);
    o2.x = fmaf((v2.x - m) * rs, G2.x, B2.x + c2.x + w2.x);
    o2.y = fmaf((v2.y - m) * rs, G2.y, B2.y + c2.y + w2.y);
    o2.z = fmaf((v2.z - m) * rs, G2.z, B2.z + c2.z + w2.z);
    o2.w = fmaf((v2.w - m) * rs, G2.w, B2.w + c2.w + w2.w);

    float4* q = out4 + (size_t)row * 12 + lane4;
    q[0] = o0; q[4] = o1; q[8] = o2;
}

// single_out = layernorm(single): same 4-lane scheme, no embedding term.
__global__ __launch_bounds__(256, 4) void single_kernel(
    const float4* __restrict__ in4,
    const float4* __restrict__ g4,
    const float4* __restrict__ be4,
    float4*       __restrict__ out4,
    int rows)
{
    const int gtid  = blockIdx.x * 256 + threadIdx.x;
    const int lane4 = gtid & 3;
    const int row   = gtid >> 2;
    if (row >= rows) return;

    const float4* p = in4 + (size_t)row * 12 + lane4;
    float4 v0 = p[0], v1 = p[4], v2 = p[8];

    float sum = v0.x + v0.y + v0.z + v0.w
              + v1.x + v1.y + v1.z + v1.w
              + v2.x + v2.y + v2.z + v2.w;
    float ssq = v0.x*v0.x + v0.y*v0.y + v0.z*v0.z + v0.w*v0.w
              + v1.x*v1.x + v1.y*v1.y + v1.z*v1.z + v1.w*v1.w
              + v2.x*v2.x + v2.y*v2.y + v2.z*v2.z + v2.w*v2.w;
    sum += __shfl_xor_sync(0xffffffffu, sum, 1);
    ssq += __shfl_xor_sync(0xffffffffu, ssq, 1);
    sum += __shfl_xor_sync(0xffffffffu, sum, 2);
    ssq += __shfl_xor_sync(0xffffffffu, ssq, 2);

    const float m   = sum * (1.0f / DIM);
    const float var = ssq * (1.0f / DIM) - m * m;
    const float rs  = rsqrtf(var + 1e-5f);

    float4 G0 = g4[lane4],  G1 = g4[lane4+4],  G2 = g4[lane4+8];
    float4 B0 = be4[lane4], B1 = be4[lane4+4], B2 = be4[lane4+8];

    float4 o0, o1, o2;
    o0.x = fmaf((v0.x - m) * rs, G0.x, B0.x);
    o0.y = fmaf((v0.y - m) * rs, G0.y, B0.y);
    o0.z = fmaf((v0.z - m) * rs, G0.z, B0.z);
    o0.w = fmaf((v0.w - m) * rs, G0.w, B0.w);
    o1.x = fmaf((v1.x - m) * rs, G1.x, B1.x);
    o1.y = fmaf((v1.y - m) * rs, G1.y, B1.y);
    o1.z = fmaf((v1.z - m) * rs, G1.z, B1.z);
    o1.w = fmaf((v1.w - m) * rs, G1.w, B1.w);
    o2.x = fmaf((v2.x - m) * rs, G2.x, B2.x);
    o2.y = fmaf((v2.y - m) * rs, G2.y, B2.y);
    o2.z = fmaf((v2.z - m) * rs, G2.z, B2.z);
    o2.w = fmaf((v2.w - m) * rs, G2.w, B2.w);

    float4* q = out4 + (size_t)row * 12 + lane4;
    q[0] = o0; q[4] = o1; q[8] = o2;
}

// ---------------------------------------------------------------------------
extern "C" void kernel_launch(void* const* d_in, const int* in_sizes, int n_in,
                              void* d_out, int out_size) {
    const float* x      = (const float*)d_in[0];
    const float* single = (const float*)d_in[1];
    const float* pair   = (const float*)d_in[2];
    const float* W      = (const float*)d_in[3];
    const float* b      = (const float*)d_in[4];
    const float* gp     = (const float*)d_in[5];
    const float* bp     = (const float*)d_in[6];
    const float* gm     = (const float*)d_in[7];
    const float* bm     = (const float*)d_in[8];

    const int L = in_sizes[1] / DIM;            // single is [1, L, DIM]

    float* out        = (float*)d_out;
    float* single_out = out;                     // (single_out, pair_out) concatenated
    float* pair_out   = out + (size_t)L * DIM;

    {
        int threads = L * 4;
        int blocks  = (threads + 255) / 256;
        single_kernel<<<blocks, 256>>>(
            (const float4*)single, (const float4*)gm, (const float4*)bm,
            (float4*)single_out, L);
    }
    {
        int total   = L * L;
        long threads = (long)total * 4;
        int blocks  = (int)((threads + 255) / 256);
        pair_kernel<<<blocks, 256>>>(
            x, (const float4*)pair, (const float4*)W, (const float4*)b,
            (const float4*)gp, (const float4*)bp,
            (float4*)pair_out, L, total);
    }
}